// round 3
// baseline (speedup 1.0000x reference)
#include <cuda_runtime.h>
#include <math.h>

// ---------------- problem constants ----------------
#define BB      2
#define NN      2048
#define DIM     2048
#define HEADS   16
#define DH      128
#define TOK     (BB*NN)          // 4096
#define FF      8192             // FF_MULT*DIM
#define QKVW    (DIM+DH)         // 2176
#define NEGMAX  (-3.402823466e38f)
#define QSCALE  0.08838834764831845f   // 128^-0.5

// ---------------- scratch (static device memory; no allocs) ----------------
__device__ float g_xn   [(size_t)TOK*DIM];          // 33.5 MB
__device__ float g_h    [(size_t)TOK*2*FF];         // 268 MB
__device__ float g_ffact[(size_t)TOK*FF];           // 134 MB
__device__ float g_ffout[(size_t)TOK*DIM];          // 33.5 MB
__device__ float g_qkv  [(size_t)TOK*QKVW];         // 35.7 MB
__device__ float g_sim  [(size_t)BB*HEADS*NN*NN];   // 537 MB
__device__ float g_ctx  [(size_t)TOK*DIM];          // 33.5 MB

// ---------------- reductions ----------------
__device__ __forceinline__ float blockReduceSum(float v) {
    __shared__ float sh[8];
    __syncthreads();
    #pragma unroll
    for (int o = 16; o > 0; o >>= 1) v += __shfl_xor_sync(0xffffffffu, v, o);
    int w = threadIdx.x >> 5, l = threadIdx.x & 31;
    if (l == 0) sh[w] = v;
    __syncthreads();
    if (w == 0) {
        v = (l < 8) ? sh[l] : 0.f;
        #pragma unroll
        for (int o = 4; o > 0; o >>= 1) v += __shfl_xor_sync(0xffffffffu, v, o);
        if (l == 0) sh[0] = v;
    }
    __syncthreads();
    return sh[0];
}

__device__ __forceinline__ float blockReduceMax(float v) {
    __shared__ float sh[8];
    __syncthreads();
    #pragma unroll
    for (int o = 16; o > 0; o >>= 1) v = fmaxf(v, __shfl_xor_sync(0xffffffffu, v, o));
    int w = threadIdx.x >> 5, l = threadIdx.x & 31;
    if (l == 0) sh[w] = v;
    __syncthreads();
    if (w == 0) {
        v = (l < 8) ? sh[l] : -INFINITY;
        #pragma unroll
        for (int o = 4; o > 0; o >>= 1) v = fmaxf(v, __shfl_xor_sync(0xffffffffu, v, o));
        if (l == 0) sh[0] = v;
    }
    __syncthreads();
    return sh[0];
}

// ---------------- 1. RMSNorm ----------------
__global__ void rmsnorm_kernel(const float* __restrict__ x, const float* __restrict__ g) {
    int row = blockIdx.x;
    const float* xr = x + (size_t)row * DIM;
    float*       o  = g_xn + (size_t)row * DIM;
    int t = threadIdx.x;
    float v[8];
    float ss = 0.f;
    #pragma unroll
    for (int i = 0; i < 8; i++) { v[i] = xr[t + i*256]; ss += v[i]*v[i]; }
    ss = blockReduceSum(ss);
    __shared__ float s_scale;
    if (t == 0) {
        float norm = sqrtf(ss * (1.0f / DIM));
        s_scale = 1.0f / fmaxf(norm, 1e-8f);
    }
    __syncthreads();
    float sc = s_scale;
    #pragma unroll
    for (int i = 0; i < 8; i++) o[t + i*256] = v[i] * sc * g[t + i*256];
}

// ---------------- generic fp32 GEMM body: C = A@B (+D), 128x128 tile ----------------
// A: MxK row-major (lda), B: KxN row-major (ldb), C: MxN row-major (ldc).
// Grid: (N/128, M/128). 256 threads, 8x8 per thread, BK=8.
// Requirements (all satisfied here): M%128==0, N%128==0, K%8==0, ld* %4==0.
__device__ __forceinline__ void gemm128_body(
    const float* __restrict__ A, int lda,
    const float* __restrict__ B, int ldb,
    float* __restrict__ C, int ldc,
    const float* __restrict__ D, int K)
{
    const int BM = 128, BN = 128, BK = 8, TM = 8, TN = 8;
    __shared__ float As[BK][BM];
    __shared__ float Bs[BK][BN];
    int tid  = threadIdx.x;
    int aRow = tid >> 1;            // 0..127
    int aCol = (tid & 1) * 4;       // 0 or 4
    int bRow = tid >> 5;            // 0..7
    int bCol = (tid & 31) * 4;      // 0..124
    int tRow = (tid >> 4) * TM;     // 0..120
    int tCol = (tid & 15) * TN;     // 0..120
    const size_t aBase = (size_t)blockIdx.y * BM * lda;
    const size_t bBase = (size_t)blockIdx.x * BN;
    float acc[TM][TN] = {};
    for (int k0 = 0; k0 < K; k0 += BK) {
        float4 av = *(const float4*)(A + aBase + (size_t)aRow * lda + k0 + aCol);
        As[aCol+0][aRow] = av.x; As[aCol+1][aRow] = av.y;
        As[aCol+2][aRow] = av.z; As[aCol+3][aRow] = av.w;
        float4 bv = *(const float4*)(B + bBase + (size_t)(k0 + bRow) * ldb + bCol);
        *(float4*)&Bs[bRow][bCol] = bv;
        __syncthreads();
        #pragma unroll
        for (int kk = 0; kk < BK; kk++) {
            float4 a0 = *(const float4*)&As[kk][tRow];
            float4 a1 = *(const float4*)&As[kk][tRow+4];
            float4 b0 = *(const float4*)&Bs[kk][tCol];
            float4 b1 = *(const float4*)&Bs[kk][tCol+4];
            float ar[8] = {a0.x,a0.y,a0.z,a0.w,a1.x,a1.y,a1.z,a1.w};
            float br[8] = {b0.x,b0.y,b0.z,b0.w,b1.x,b1.y,b1.z,b1.w};
            #pragma unroll
            for (int i = 0; i < TM; i++)
                #pragma unroll
                for (int j = 0; j < TN; j++)
                    acc[i][j] += ar[i] * br[j];
        }
        __syncthreads();
    }
    size_t cBase = (size_t)(blockIdx.y * BM + tRow) * ldc + blockIdx.x * BN + tCol;
    #pragma unroll
    for (int i = 0; i < TM; i++) {
        #pragma unroll
        for (int j = 0; j < TN; j += 4) {
            size_t off = cBase + (size_t)i * ldc + j;
            float4 v = make_float4(acc[i][j], acc[i][j+1], acc[i][j+2], acc[i][j+3]);
            if (D) {
                float4 dv = *(const float4*)(D + off);
                v.x += dv.x; v.y += dv.y; v.z += dv.z; v.w += dv.w;
            }
            *(float4*)(C + off) = v;
        }
    }
}

__global__ void __launch_bounds__(256) sgemm_nn(
    const float* __restrict__ A, int lda,
    const float* __restrict__ B, int ldb,
    float* __restrict__ C, int ldc,
    const float* __restrict__ D, int K)
{
    gemm128_body(A, lda, B, ldb, C, ldc, D, K);
}

// ---------------- 3. SwiGLU activation ----------------
__global__ void silu_mul_kernel() {
    size_t i4 = ((size_t)blockIdx.x * blockDim.x + threadIdx.x) * 4;  // over TOK*FF
    size_t r = i4 / FF, c = i4 % FF;
    const float4 val  = *(const float4*)&g_h[r * (2*(size_t)FF) + c];
    const float4 gate = *(const float4*)&g_h[r * (2*(size_t)FF) + FF + c];
    float4 o;
    o.x = val.x * (gate.x / (1.f + expf(-gate.x)));
    o.y = val.y * (gate.y / (1.f + expf(-gate.y)));
    o.z = val.z * (gate.z / (1.f + expf(-gate.z)));
    o.w = val.w * (gate.w / (1.f + expf(-gate.w)));
    *(float4*)&g_ffact[r * (size_t)FF + c] = o;
}

// ---------------- 6. sim = (q*scale) @ kv^T + alibi + causal ----------------
// Grid: (N/64 jTiles, N/64 iTiles, B*HEADS). 256 threads, 4x4 per thread.
__global__ void __launch_bounds__(256) attn_sim_kernel() {
    int z = blockIdx.z, b = z >> 4, h = z & 15;
    int iBase = blockIdx.y * 64, jBase = blockIdx.x * 64;
    int tid  = threadIdx.x;
    int tRow = (tid >> 4) * 4;
    int tCol = (tid & 15) * 4;
    float* S = g_sim + (size_t)z * NN * NN;

    if (jBase > iBase + 63) {   // fully masked tile
        #pragma unroll
        for (int ii = 0; ii < 4; ii++) {
            float4 v = make_float4(NEGMAX, NEGMAX, NEGMAX, NEGMAX);
            *(float4*)&S[(size_t)(iBase + tRow + ii) * NN + jBase + tCol] = v;
        }
        return;
    }

    const float* Q  = g_qkv + (size_t)b * NN * QKVW + h * DH;
    const float* KV = g_qkv + (size_t)b * NN * QKVW + DIM;
    __shared__ float As[16][64];
    __shared__ float Bs[16][64];
    int loadRow = tid >> 2;            // 0..63
    int loadCol = (tid & 3) * 4;       // 0,4,8,12
    float acc[4][4] = {};
    for (int k0 = 0; k0 < DH; k0 += 16) {
        float4 qa = *(const float4*)(Q  + (size_t)(iBase + loadRow) * QKVW + k0 + loadCol);
        As[loadCol+0][loadRow] = qa.x; As[loadCol+1][loadRow] = qa.y;
        As[loadCol+2][loadRow] = qa.z; As[loadCol+3][loadRow] = qa.w;
        float4 kb = *(const float4*)(KV + (size_t)(jBase + loadRow) * QKVW + k0 + loadCol);
        Bs[loadCol+0][loadRow] = kb.x; Bs[loadCol+1][loadRow] = kb.y;
        Bs[loadCol+2][loadRow] = kb.z; Bs[loadCol+3][loadRow] = kb.w;
        __syncthreads();
        #pragma unroll
        for (int kk = 0; kk < 16; kk++) {
            float4 a = *(const float4*)&As[kk][tRow];
            float4 c = *(const float4*)&Bs[kk][tCol];
            float ar[4] = {a.x,a.y,a.z,a.w};
            float br[4] = {c.x,c.y,c.z,c.w};
            #pragma unroll
            for (int i = 0; i < 4; i++)
                #pragma unroll
                for (int j = 0; j < 4; j++)
                    acc[i][j] += ar[i] * br[j];
        }
        __syncthreads();
    }
    float slope = exp2f(-0.5f * (float)(h + 1));
    #pragma unroll
    for (int ii = 0; ii < 4; ii++) {
        int i = iBase + tRow + ii;
        float4 v;
        float* vp = &v.x;
        #pragma unroll
        for (int jj = 0; jj < 4; jj++) {
            int j = jBase + tCol + jj;
            vp[jj] = (j > i) ? NEGMAX
                             : acc[ii][jj] * QSCALE - (float)(i - j) * slope;
        }
        *(float4*)&S[(size_t)i * NN + jBase + tCol] = v;
    }
}

// ---------------- 7. row softmax over g_sim ----------------
__global__ void softmax_kernel() {
    float* p = g_sim + (size_t)blockIdx.x * NN;
    int t = threadIdx.x;
    float v[8];
    float m = -INFINITY;
    #pragma unroll
    for (int i = 0; i < 8; i++) { v[i] = p[t + i*256]; m = fmaxf(m, v[i]); }
    m = blockReduceMax(m);
    float s = 0.f;
    #pragma unroll
    for (int i = 0; i < 8; i++) { v[i] = expf(v[i] - m); s += v[i]; }
    s = blockReduceSum(s);
    float inv = 1.f / s;
    #pragma unroll
    for (int i = 0; i < 8; i++) p[t + i*256] = v[i] * inv;
}

// ---------------- 8. ctx = attn @ kv (per b,h) ----------------
// Grid: (1, N/128, B*HEADS)
__global__ void __launch_bounds__(256) attn_v_kernel() {
    int z = blockIdx.z, b = z >> 4, h = z & 15;
    const float* A  = g_sim + (size_t)z * NN * NN;                 // 2048 x 2048
    const float* Bv = g_qkv + (size_t)b * NN * QKVW + DIM;         // 2048 x 128 (ldb QKVW)
    float*       C  = g_ctx + (size_t)b * NN * DIM + h * DH;       // ldc DIM
    gemm128_body(A, NN, Bv, QKVW, C, DIM, nullptr, NN);
}

// ---------------- launch ----------------
extern "C" void kernel_launch(void* const* d_in, const int* in_sizes, int n_in,
                              void* d_out, int out_size) {
    const float* x          = (const float*)d_in[0];
    const float* g          = (const float*)d_in[1];
    const float* w_qkv      = (const float*)d_in[2];
    const float* w_attn_out = (const float*)d_in[3];
    const float* w_ff1      = (const float*)d_in[4];
    const float* w_ff2      = (const float*)d_in[5];
    float* out = (float*)d_out;

    float *xn, *h, *ffact, *ffout, *qkv, *ctx;
    cudaGetSymbolAddress((void**)&xn,    g_xn);
    cudaGetSymbolAddress((void**)&h,     g_h);
    cudaGetSymbolAddress((void**)&ffact, g_ffact);
    cudaGetSymbolAddress((void**)&ffout, g_ffout);
    cudaGetSymbolAddress((void**)&qkv,   g_qkv);
    cudaGetSymbolAddress((void**)&ctx,   g_ctx);

    // 1. xn = rmsnorm(x) * g
    rmsnorm_kernel<<<TOK, 256>>>(x, g);
    // 2. h = xn @ w_ff1                 (4096 x 2048) @ (2048 x 16384)
    sgemm_nn<<<dim3(2*FF/128, TOK/128), 256>>>(xn, DIM, w_ff1, 2*FF, h, 2*FF, nullptr, DIM);
    // 3. ffact = silu(gate) * val
    silu_mul_kernel<<<(TOK*(size_t)FF)/4/256, 256>>>();
    // 4. ffout = ffact @ w_ff2          (4096 x 8192) @ (8192 x 2048)
    sgemm_nn<<<dim3(DIM/128, TOK/128), 256>>>(ffact, FF, w_ff2, DIM, ffout, DIM, nullptr, FF);
    // 5. qkv = xn @ w_qkv               (4096 x 2048) @ (2048 x 2176)
    sgemm_nn<<<dim3(QKVW/128, TOK/128), 256>>>(xn, DIM, w_qkv, QKVW, qkv, QKVW, nullptr, DIM);
    // 6. sim = scaled q @ kv^T + alibi + causal mask
    attn_sim_kernel<<<dim3(NN/64, NN/64, BB*HEADS), 256>>>();
    // 7. softmax rows
    softmax_kernel<<<BB*HEADS*NN, 256>>>();
    // 8. ctx = attn @ kv
    attn_v_kernel<<<dim3(1, NN/128, BB*HEADS), 256>>>();
    // 9. out = ctx @ w_attn_out + ffout
    sgemm_nn<<<dim3(DIM/128, TOK/128), 256>>>(ctx, DIM, w_attn_out, DIM, out, DIM, ffout, DIM);
}

// round 8
// speedup vs baseline: 2.4139x; 2.4139x over previous
#include <cuda_runtime.h>
#include <cuda_bf16.h>
#include <cstdint>
#include <math.h>

// ---------------- problem constants ----------------
#define BB      2
#define NN      2048
#define DIM     2048
#define HEADS   16
#define DH      128
#define TOK     (BB*NN)          // 4096
#define FF      8192             // FF_MULT*DIM
#define QKVW    (DIM+DH)         // 2176
#define NEGMAX  (-3.402823466e38f)
#define QSCALE  0.08838834764831845f   // 128^-0.5

typedef __nv_bfloat16 bf16;

// ---------------- scratch (static device memory; no allocs) ----------------
__device__ bf16  g_xnh  [(size_t)TOK*DIM];
__device__ bf16  g_xnl  [(size_t)TOK*DIM];
__device__ float g_h    [(size_t)TOK*2*FF];
__device__ bf16  g_ffah [(size_t)TOK*FF];
__device__ bf16  g_ffal [(size_t)TOK*FF];
__device__ float g_ffout[(size_t)TOK*DIM];
__device__ float g_qkv  [(size_t)TOK*QKVW];
__device__ float g_sim  [(size_t)BB*HEADS*NN*NN];
__device__ bf16  g_ph   [(size_t)BB*HEADS*NN*NN];   // softmax probs hi
__device__ bf16  g_pl   [(size_t)BB*HEADS*NN*NN];   // softmax probs lo
__device__ bf16  g_kvh  [(size_t)TOK*DH];
__device__ bf16  g_kvl  [(size_t)TOK*DH];
__device__ float g_ctx  [(size_t)TOK*DIM];
__device__ bf16  g_ctxh [(size_t)TOK*DIM];
__device__ bf16  g_ctxl [(size_t)TOK*DIM];
__device__ bf16  g_wff1h[(size_t)DIM*2*FF];
__device__ bf16  g_wff1l[(size_t)DIM*2*FF];
__device__ bf16  g_wff2h[(size_t)FF*DIM];
__device__ bf16  g_wff2l[(size_t)FF*DIM];
__device__ bf16  g_wqkvh[(size_t)DIM*QKVW];
__device__ bf16  g_wqkvl[(size_t)DIM*QKVW];
__device__ bf16  g_waoh [(size_t)DIM*DIM];
__device__ bf16  g_waol [(size_t)DIM*DIM];

// ---------------- PTX helpers ----------------
__device__ __forceinline__ uint32_t smem_u32(const void* p) {
    uint32_t a;
    asm("{ .reg .u64 t; cvta.to.shared.u64 t, %1; cvt.u32.u64 %0, t; }" : "=r"(a) : "l"(p));
    return a;
}
__device__ __forceinline__ void cp16(uint32_t dst, const void* src) {
    asm volatile("cp.async.cg.shared.global [%0], [%1], 16;" :: "r"(dst), "l"(src));
}
__device__ __forceinline__ void cp_commit() { asm volatile("cp.async.commit_group;"); }
template<int W> __device__ __forceinline__ void cp_wait() {
    asm volatile("cp.async.wait_group %0;" :: "n"(W));
}
__device__ __forceinline__ void ldm_x4(uint32_t r[4], uint32_t addr) {
    asm volatile("ldmatrix.sync.aligned.m8n8.x4.shared.b16 {%0,%1,%2,%3}, [%4];"
                 : "=r"(r[0]), "=r"(r[1]), "=r"(r[2]), "=r"(r[3]) : "r"(addr));
}
__device__ __forceinline__ void ldm_x4t(uint32_t r[4], uint32_t addr) {
    asm volatile("ldmatrix.sync.aligned.m8n8.x4.trans.shared.b16 {%0,%1,%2,%3}, [%4];"
                 : "=r"(r[0]), "=r"(r[1]), "=r"(r[2]), "=r"(r[3]) : "r"(addr));
}
__device__ __forceinline__ void mma_bf16(float c[4], const uint32_t a[4], const uint32_t b[2]) {
    asm volatile("mma.sync.aligned.m16n8k16.row.col.f32.bf16.bf16.f32 "
                 "{%0,%1,%2,%3}, {%4,%5,%6,%7}, {%8,%9}, {%0,%1,%2,%3};"
                 : "+f"(c[0]), "+f"(c[1]), "+f"(c[2]), "+f"(c[3])
                 : "r"(a[0]), "r"(a[1]), "r"(a[2]), "r"(a[3]), "r"(b[0]), "r"(b[1]));
}

// ---------------- split helpers ----------------
__device__ __forceinline__ void split1(float x, bf16& h, bf16& l) {
    h = __float2bfloat16(x);
    l = __float2bfloat16(x - __bfloat162float(h));
}

__global__ void split_kernel(const float* __restrict__ src,
                             bf16* __restrict__ hi, bf16* __restrict__ lo) {
    size_t i = ((size_t)blockIdx.x * blockDim.x + threadIdx.x) * 4;
    float4 v = *(const float4*)(src + i);
    bf16 h[4], l[4];
    split1(v.x, h[0], l[0]); split1(v.y, h[1], l[1]);
    split1(v.z, h[2], l[2]); split1(v.w, h[3], l[3]);
    *(uint2*)(hi + i) = *(uint2*)h;
    *(uint2*)(lo + i) = *(uint2*)l;
}

// extract kv columns [DIM, QKVW) of g_qkv into compact hi/lo (TOK x DH)
__global__ void split_kv_kernel() {
    size_t i = ((size_t)blockIdx.x * blockDim.x + threadIdx.x) * 4;  // over TOK*DH
    size_t t = i / DH, c = i % DH;
    float4 v = *(const float4*)&g_qkv[t * QKVW + DIM + c];
    bf16 h[4], l[4];
    split1(v.x, h[0], l[0]); split1(v.y, h[1], l[1]);
    split1(v.z, h[2], l[2]); split1(v.w, h[3], l[3]);
    *(uint2*)(g_kvh + i) = *(uint2*)h;
    *(uint2*)(g_kvl + i) = *(uint2*)l;
}

// ---------------- reductions ----------------
__device__ __forceinline__ float blockReduceSum(float v) {
    __shared__ float sh[8];
    __syncthreads();
    #pragma unroll
    for (int o = 16; o > 0; o >>= 1) v += __shfl_xor_sync(0xffffffffu, v, o);
    int w = threadIdx.x >> 5, l = threadIdx.x & 31;
    if (l == 0) sh[w] = v;
    __syncthreads();
    if (w == 0) {
        v = (l < 8) ? sh[l] : 0.f;
        #pragma unroll
        for (int o = 4; o > 0; o >>= 1) v += __shfl_xor_sync(0xffffffffu, v, o);
        if (l == 0) sh[0] = v;
    }
    __syncthreads();
    return sh[0];
}
__device__ __forceinline__ float blockReduceMax(float v) {
    __shared__ float sh[8];
    __syncthreads();
    #pragma unroll
    for (int o = 16; o > 0; o >>= 1) v = fmaxf(v, __shfl_xor_sync(0xffffffffu, v, o));
    int w = threadIdx.x >> 5, l = threadIdx.x & 31;
    if (l == 0) sh[w] = v;
    __syncthreads();
    if (w == 0) {
        v = (l < 8) ? sh[l] : -INFINITY;
        #pragma unroll
        for (int o = 4; o > 0; o >>= 1) v = fmaxf(v, __shfl_xor_sync(0xffffffffu, v, o));
        if (l == 0) sh[0] = v;
    }
    __syncthreads();
    return sh[0];
}

// ---------------- 1. RMSNorm -> split bf16 hi/lo ----------------
__global__ void rmsnorm_kernel(const float* __restrict__ x, const float* __restrict__ g) {
    int row = blockIdx.x;
    const float* xr = x + (size_t)row * DIM;
    bf16* oh = g_xnh + (size_t)row * DIM;
    bf16* ol = g_xnl + (size_t)row * DIM;
    int t = threadIdx.x;
    float v[8];
    float ss = 0.f;
    #pragma unroll
    for (int i = 0; i < 8; i++) { v[i] = xr[t + i*256]; ss += v[i]*v[i]; }
    ss = blockReduceSum(ss);
    __shared__ float s_scale;
    if (t == 0) {
        float norm = sqrtf(ss * (1.0f / DIM));
        s_scale = 1.0f / fmaxf(norm, 1e-8f);
    }
    __syncthreads();
    float sc = s_scale;
    #pragma unroll
    for (int i = 0; i < 8; i++) {
        float o = v[i] * sc * g[t + i*256];
        bf16 h, l; split1(o, h, l);
        oh[t + i*256] = h; ol[t + i*256] = l;
    }
}

// ============ HMMA split-bf16 GEMM: C = Ah*Bh + Ah*Bl + Al*Bh (+D) ============
// A: MxK row-major bf16 hi/lo (lda=K). B: KxN row-major bf16 hi/lo (ldb=N).
// CTA tile 128x128, BK=32, 256 threads = 8 warps (4m x 2n), warp tile 32x64.
// SMEM: padded strides -> conflict-free ldmatrix. Double-buffered cp.async.
#define ASTRIDE 80      // bytes per A smem row (40 bf16, rows 128)
#define BSTRIDE 272     // bytes per B smem row (136 bf16, rows 32)
#define AH_OFF  0
#define AL_OFF  10240
#define BH_OFF  20480
#define BL_OFF  29184
#define STAGE   37888
#define GEMM_SMEM (2*STAGE)   // 75776 B

__device__ __forceinline__ void tc_body(
    const bf16* __restrict__ Ah, const bf16* __restrict__ Al,
    const bf16* __restrict__ Bh, const bf16* __restrict__ Bl,
    float* __restrict__ C, const float* __restrict__ Dadd,
    int N, int K, int ldc, int m0, int n0)
{
    extern __shared__ char smem[];
    uint32_t sb = smem_u32(smem);
    const int tid = threadIdx.x, wid = tid >> 5, lane = tid & 31;
    const int wm = wid >> 1, wn = wid & 1;

    float acc[2][8][4] = {};

    auto load_chunk = [&](int c, int buf) {
        uint32_t base = sb + buf * STAGE;
        int k0 = c * 32;
        #pragma unroll
        for (int i = 0; i < 2; i++) {                 // A: 512 lines hi + 512 lo
            int l = tid + i * 256;
            int row = l >> 2, kc = (l & 3) * 8;
            size_t go = (size_t)(m0 + row) * K + k0 + kc;
            uint32_t so = (uint32_t)(row * ASTRIDE + kc * 2);
            cp16(base + AH_OFF + so, Ah + go);
            cp16(base + AL_OFF + so, Al + go);
        }
        #pragma unroll
        for (int i = 0; i < 2; i++) {                 // B: 512 lines hi + 512 lo
            int l = tid + i * 256;
            int kr = l >> 4, nc = (l & 15) * 8;
            size_t go = (size_t)(k0 + kr) * N + n0 + nc;
            uint32_t so = (uint32_t)(kr * BSTRIDE + nc * 2);
            cp16(base + BH_OFF + so, Bh + go);
            cp16(base + BL_OFF + so, Bl + go);
        }
        cp_commit();
    };

    const int NC = K >> 5;
    load_chunk(0, 0);
    cp_wait<0>(); __syncthreads();
    for (int c = 0; c < NC; c++) {
        int buf = c & 1;
        if (c + 1 < NC) load_chunk(c + 1, buf ^ 1);
        uint32_t base = sb + buf * STAGE;
        #pragma unroll
        for (int ks = 0; ks < 2; ks++) {
            uint32_t aH[2][4], aL[2][4], bH[8][2], bL[8][2];
            #pragma unroll
            for (int mt = 0; mt < 2; mt++) {
                int row = wm * 32 + mt * 16 + (lane & 15);
                int col = ks * 16 + (lane >> 4) * 8;
                uint32_t off = (uint32_t)(row * ASTRIDE + col * 2);
                ldm_x4(aH[mt], base + AH_OFF + off);
                ldm_x4(aL[mt], base + AL_OFF + off);
            }
            #pragma unroll
            for (int np = 0; np < 4; np++) {
                int kr = ks * 16 + (lane & 15);
                int nc = wn * 64 + np * 16 + (lane >> 4) * 8;
                uint32_t off = (uint32_t)(kr * BSTRIDE + nc * 2);
                uint32_t th[4], tl[4];
                ldm_x4t(th, base + BH_OFF + off);
                ldm_x4t(tl, base + BL_OFF + off);
                bH[np*2][0] = th[0]; bH[np*2][1] = th[1];
                bH[np*2+1][0] = th[2]; bH[np*2+1][1] = th[3];
                bL[np*2][0] = tl[0]; bL[np*2][1] = tl[1];
                bL[np*2+1][0] = tl[2]; bL[np*2+1][1] = tl[3];
            }
            #pragma unroll
            for (int mt = 0; mt < 2; mt++)
                #pragma unroll
                for (int nt = 0; nt < 8; nt++) {
                    mma_bf16(acc[mt][nt], aH[mt], bH[nt]);
                    mma_bf16(acc[mt][nt], aH[mt], bL[nt]);
                    mma_bf16(acc[mt][nt], aL[mt], bH[nt]);
                }
        }
        if (c + 1 < NC) { cp_wait<0>(); __syncthreads(); }
    }

    // epilogue: fragment (r, r+8) x (col pair)
    #pragma unroll
    for (int mt = 0; mt < 2; mt++) {
        int r0 = m0 + wm * 32 + mt * 16 + (lane >> 2);
        #pragma unroll
        for (int nt = 0; nt < 8; nt++) {
            int cc = n0 + wn * 64 + nt * 8 + (lane & 3) * 2;
            float2 v0 = make_float2(acc[mt][nt][0], acc[mt][nt][1]);
            float2 v1 = make_float2(acc[mt][nt][2], acc[mt][nt][3]);
            size_t o0 = (size_t)r0 * ldc + cc;
            size_t o1 = o0 + (size_t)8 * ldc;
            if (Dadd) {
                float2 d0 = *(const float2*)(Dadd + o0);
                float2 d1 = *(const float2*)(Dadd + o1);
                v0.x += d0.x; v0.y += d0.y; v1.x += d1.x; v1.y += d1.y;
            }
            *(float2*)(C + o0) = v0;
            *(float2*)(C + o1) = v1;
        }
    }
}

__global__ void __launch_bounds__(256, 1) tc_gemm(
    const bf16* __restrict__ Ah, const bf16* __restrict__ Al,
    const bf16* __restrict__ Bh, const bf16* __restrict__ Bl,
    float* __restrict__ C, const float* __restrict__ Dadd,
    int N, int K, int ldc)
{
    tc_body(Ah, Al, Bh, Bl, C, Dadd, N, K, ldc, blockIdx.y * 128, blockIdx.x * 128);
}

// attn_v: ctx[b,:,h*DH:...] = probs[z] @ kv[b]   (z = b*16+h)
__global__ void __launch_bounds__(256, 1) attn_v_tc() {
    int z = blockIdx.z, b = z >> 4, h = z & 15;
    const bf16* Ah = g_ph + (size_t)z * NN * NN;
    const bf16* Al = g_pl + (size_t)z * NN * NN;
    const bf16* Bh = g_kvh + (size_t)b * NN * DH;
    const bf16* Bl = g_kvl + (size_t)b * NN * DH;
    float* C = g_ctx + (size_t)b * NN * DIM + h * DH;
    tc_body(Ah, Al, Bh, Bl, C, nullptr, DH, NN, DIM, blockIdx.y * 128, 0);
}

// ---------------- 3. SwiGLU activation -> split bf16 hi/lo ----------------
__global__ void silu_split_kernel() {
    size_t i4 = ((size_t)blockIdx.x * blockDim.x + threadIdx.x) * 4;
    size_t r = i4 / FF, c = i4 % FF;
    const float4 val  = *(const float4*)&g_h[r * (2*(size_t)FF) + c];
    const float4 gate = *(const float4*)&g_h[r * (2*(size_t)FF) + FF + c];
    float o[4];
    o[0] = val.x * (gate.x / (1.f + expf(-gate.x)));
    o[1] = val.y * (gate.y / (1.f + expf(-gate.y)));
    o[2] = val.z * (gate.z / (1.f + expf(-gate.z)));
    o[3] = val.w * (gate.w / (1.f + expf(-gate.w)));
    bf16 h[4], l[4];
    #pragma unroll
    for (int i = 0; i < 4; i++) split1(o[i], h[i], l[i]);
    size_t off = r * (size_t)FF + c;
    *(uint2*)(g_ffah + off) = *(uint2*)h;
    *(uint2*)(g_ffal + off) = *(uint2*)l;
}

// ---------------- 6. sim = (q*scale) @ kv^T + alibi + causal (fp32) ---------
__global__ void __launch_bounds__(256) attn_sim_kernel() {
    int z = blockIdx.z, b = z >> 4, h = z & 15;
    int iBase = blockIdx.y * 64, jBase = blockIdx.x * 64;
    int tid  = threadIdx.x;
    int tRow = (tid >> 4) * 4;
    int tCol = (tid & 15) * 4;
    float* S = g_sim + (size_t)z * NN * NN;

    if (jBase > iBase + 63) {
        #pragma unroll
        for (int ii = 0; ii < 4; ii++) {
            float4 v = make_float4(NEGMAX, NEGMAX, NEGMAX, NEGMAX);
            *(float4*)&S[(size_t)(iBase + tRow + ii) * NN + jBase + tCol] = v;
        }
        return;
    }

    const float* Q  = g_qkv + (size_t)b * NN * QKVW + h * DH;
    const float* KV = g_qkv + (size_t)b * NN * QKVW + DIM;
    __shared__ float As[16][64];
    __shared__ float Bs[16][64];
    int loadRow = tid >> 2;
    int loadCol = (tid & 3) * 4;
    float acc[4][4] = {};
    for (int k0 = 0; k0 < DH; k0 += 16) {
        float4 qa = *(const float4*)(Q  + (size_t)(iBase + loadRow) * QKVW + k0 + loadCol);
        As[loadCol+0][loadRow] = qa.x; As[loadCol+1][loadRow] = qa.y;
        As[loadCol+2][loadRow] = qa.z; As[loadCol+3][loadRow] = qa.w;
        float4 kb = *(const float4*)(KV + (size_t)(jBase + loadRow) * QKVW + k0 + loadCol);
        Bs[loadCol+0][loadRow] = kb.x; Bs[loadCol+1][loadRow] = kb.y;
        Bs[loadCol+2][loadRow] = kb.z; Bs[loadCol+3][loadRow] = kb.w;
        __syncthreads();
        #pragma unroll
        for (int kk = 0; kk < 16; kk++) {
            float4 a = *(const float4*)&As[kk][tRow];
            float4 c = *(const float4*)&Bs[kk][tCol];
            float ar[4] = {a.x,a.y,a.z,a.w};
            float br[4] = {c.x,c.y,c.z,c.w};
            #pragma unroll
            for (int i = 0; i < 4; i++)
                #pragma unroll
                for (int j = 0; j < 4; j++)
                    acc[i][j] += ar[i] * br[j];
        }
        __syncthreads();
    }
    float slope = exp2f(-0.5f * (float)(h + 1));
    #pragma unroll
    for (int ii = 0; ii < 4; ii++) {
        int i = iBase + tRow + ii;
        float4 v;
        float* vp = &v.x;
        #pragma unroll
        for (int jj = 0; jj < 4; jj++) {
            int j = jBase + tCol + jj;
            vp[jj] = (j > i) ? NEGMAX
                             : acc[ii][jj] * QSCALE - (float)(i - j) * slope;
        }
        *(float4*)&S[(size_t)i * NN + jBase + tCol] = v;
    }
}

// ---------------- 7. row softmax -> split bf16 probs hi/lo ----------------
__global__ void softmax_kernel() {
    size_t rowoff = (size_t)blockIdx.x * NN;
    const float* p = g_sim + rowoff;
    bf16* oh = g_ph + rowoff;
    bf16* ol = g_pl + rowoff;
    int t = threadIdx.x;
    float v[8];
    float m = -INFINITY;
    #pragma unroll
    for (int i = 0; i < 8; i++) { v[i] = p[t + i*256]; m = fmaxf(m, v[i]); }
    m = blockReduceMax(m);
    float s = 0.f;
    #pragma unroll
    for (int i = 0; i < 8; i++) { v[i] = expf(v[i] - m); s += v[i]; }
    s = blockReduceSum(s);
    float inv = 1.f / s;
    #pragma unroll
    for (int i = 0; i < 8; i++) {
        bf16 h, l; split1(v[i] * inv, h, l);
        oh[t + i*256] = h; ol[t + i*256] = l;
    }
}

// ---------------- launch ----------------
extern "C" void kernel_launch(void* const* d_in, const int* in_sizes, int n_in,
                              void* d_out, int out_size) {
    const float* x          = (const float*)d_in[0];
    const float* g          = (const float*)d_in[1];
    const float* w_qkv      = (const float*)d_in[2];
    const float* w_attn_out = (const float*)d_in[3];
    const float* w_ff1      = (const float*)d_in[4];
    const float* w_ff2      = (const float*)d_in[5];
    float* out = (float*)d_out;

    static bool attr_done = false;
    if (!attr_done) {
        cudaFuncSetAttribute(tc_gemm,   cudaFuncAttributeMaxDynamicSharedMemorySize, GEMM_SMEM);
        cudaFuncSetAttribute(attn_v_tc, cudaFuncAttributeMaxDynamicSharedMemorySize, GEMM_SMEM);
        attr_done = true;
    }

    float *hbuf, *ffout, *qkv, *ctx;
    bf16 *xnh, *xnl, *ffah, *ffal, *ctxh, *ctxl;
    bf16 *wff1h, *wff1l, *wff2h, *wff2l, *wqkvh, *wqkvl, *waoh, *waol;
    cudaGetSymbolAddress((void**)&hbuf,  g_h);
    cudaGetSymbolAddress((void**)&ffout, g_ffout);
    cudaGetSymbolAddress((void**)&qkv,   g_qkv);
    cudaGetSymbolAddress((void**)&ctx,   g_ctx);
    cudaGetSymbolAddress((void**)&xnh,   g_xnh);
    cudaGetSymbolAddress((void**)&xnl,   g_xnl);
    cudaGetSymbolAddress((void**)&ffah,  g_ffah);
    cudaGetSymbolAddress((void**)&ffal,  g_ffal);
    cudaGetSymbolAddress((void**)&ctxh,  g_ctxh);
    cudaGetSymbolAddress((void**)&ctxl,  g_ctxl);
    cudaGetSymbolAddress((void**)&wff1h, g_wff1h);
    cudaGetSymbolAddress((void**)&wff1l, g_wff1l);
    cudaGetSymbolAddress((void**)&wff2h, g_wff2h);
    cudaGetSymbolAddress((void**)&wff2l, g_wff2l);
    cudaGetSymbolAddress((void**)&wqkvh, g_wqkvh);
    cudaGetSymbolAddress((void**)&wqkvl, g_wqkvl);
    cudaGetSymbolAddress((void**)&waoh,  g_waoh);
    cudaGetSymbolAddress((void**)&waol,  g_waol);

    // weight splits (fp32 -> bf16 hi/lo)
    split_kernel<<<(size_t)DIM*2*FF/1024, 256>>>(w_ff1,      wff1h, wff1l);
    split_kernel<<<(size_t)FF*DIM/1024,   256>>>(w_ff2,      wff2h, wff2l);
    split_kernel<<<(size_t)DIM*QKVW/1024, 256>>>(w_qkv,      wqkvh, wqkvl);
    split_kernel<<<(size_t)DIM*DIM/1024,  256>>>(w_attn_out, waoh,  waol);

    // 1. xn = rmsnorm(x)*g  (split output)
    rmsnorm_kernel<<<TOK, 256>>>(x, g);
    // 2. h = xn @ w_ff1
    tc_gemm<<<dim3(2*FF/128, TOK/128), 256, GEMM_SMEM>>>(
        xnh, xnl, wff1h, wff1l, hbuf, nullptr, 2*FF, DIM, 2*FF);
    // 3. ffact = silu(gate)*val  (split output)
    silu_split_kernel<<<(size_t)TOK*FF/1024, 256>>>();
    // 4. ffout = ffact @ w_ff2
    tc_gemm<<<dim3(DIM/128, TOK/128), 256, GEMM_SMEM>>>(
        ffah, ffal, wff2h, wff2l, ffout, nullptr, DIM, FF, DIM);
    // 5. qkv = xn @ w_qkv
    tc_gemm<<<dim3(QKVW/128, TOK/128), 256, GEMM_SMEM>>>(
        xnh, xnl, wqkvh, wqkvl, qkv, nullptr, QKVW, DIM, QKVW);
    // 6. sim = scaled q @ kv^T + alibi + causal (fp32)
    attn_sim_kernel<<<dim3(NN/64, NN/64, BB*HEADS), 256>>>();
    // 7. softmax rows -> probs hi/lo bf16
    softmax_kernel<<<BB*HEADS*NN, 256>>>();
    // 7b. split kv hi/lo (compact)
    split_kv_kernel<<<(size_t)TOK*DH/1024, 256>>>();
    // 8. ctx = probs @ kv  (HMMA)
    attn_v_tc<<<dim3(1, NN/128, BB*HEADS), 256, GEMM_SMEM>>>();
    // 9. split ctx, then out = ctx @ w_attn_out + ffout
    split_kernel<<<(size_t)TOK*DIM/1024, 256>>>(ctx, ctxh, ctxl);
    tc_gemm<<<dim3(DIM/128, TOK/128), 256, GEMM_SMEM>>>(
        ctxh, ctxl, waoh, waol, out, ffout, DIM, DIM, DIM);
}

// round 9
// speedup vs baseline: 2.6035x; 1.0785x over previous
#include <cuda_runtime.h>
#include <cuda_bf16.h>
#include <cstdint>
#include <math.h>

// ---------------- problem constants ----------------
#define BB      2
#define NN      2048
#define DIM     2048
#define HEADS   16
#define DH      128
#define TOK     (BB*NN)          // 4096
#define FF      8192             // FF_MULT*DIM
#define QKVW    (DIM+DH)         // 2176
#define NEGMAX  (-3.402823466e38f)
#define QSCALE  0.08838834764831845f   // 128^-0.5

typedef __nv_bfloat16 bf16;

// ---------------- scratch (static device memory; no allocs) ----------------
__device__ bf16  g_xnh  [(size_t)TOK*DIM];
__device__ bf16  g_xnl  [(size_t)TOK*DIM];
__device__ float g_h    [(size_t)TOK*2*FF];
__device__ bf16  g_ffah [(size_t)TOK*FF];
__device__ bf16  g_ffal [(size_t)TOK*FF];
__device__ float g_ffout[(size_t)TOK*DIM];
__device__ float g_qkv  [(size_t)TOK*QKVW];
__device__ float g_sim  [(size_t)BB*HEADS*NN*NN];
__device__ bf16  g_ph   [(size_t)BB*HEADS*NN*NN];   // softmax probs hi
__device__ bf16  g_pl   [(size_t)BB*HEADS*NN*NN];   // softmax probs lo
__device__ bf16  g_qh   [(size_t)TOK*DIM];          // q (pre-scaled) hi
__device__ bf16  g_ql   [(size_t)TOK*DIM];          // q lo
__device__ bf16  g_kvh  [(size_t)TOK*DH];
__device__ bf16  g_kvl  [(size_t)TOK*DH];
__device__ float g_ctx  [(size_t)TOK*DIM];
__device__ bf16  g_ctxh [(size_t)TOK*DIM];
__device__ bf16  g_ctxl [(size_t)TOK*DIM];
__device__ bf16  g_wff1h[(size_t)DIM*2*FF];
__device__ bf16  g_wff1l[(size_t)DIM*2*FF];
__device__ bf16  g_wff2h[(size_t)FF*DIM];
__device__ bf16  g_wff2l[(size_t)FF*DIM];
__device__ bf16  g_wqkvh[(size_t)DIM*QKVW];
__device__ bf16  g_wqkvl[(size_t)DIM*QKVW];
__device__ bf16  g_waoh [(size_t)DIM*DIM];
__device__ bf16  g_waol [(size_t)DIM*DIM];

// ---------------- PTX helpers ----------------
__device__ __forceinline__ uint32_t smem_u32(const void* p) {
    uint32_t a;
    asm("{ .reg .u64 t; cvta.to.shared.u64 t, %1; cvt.u32.u64 %0, t; }" : "=r"(a) : "l"(p));
    return a;
}
__device__ __forceinline__ void cp16(uint32_t dst, const void* src) {
    asm volatile("cp.async.cg.shared.global [%0], [%1], 16;" :: "r"(dst), "l"(src));
}
__device__ __forceinline__ void cp_commit() { asm volatile("cp.async.commit_group;"); }
template<int W> __device__ __forceinline__ void cp_wait() {
    asm volatile("cp.async.wait_group %0;" :: "n"(W));
}
__device__ __forceinline__ void ldm_x4(uint32_t r[4], uint32_t addr) {
    asm volatile("ldmatrix.sync.aligned.m8n8.x4.shared.b16 {%0,%1,%2,%3}, [%4];"
                 : "=r"(r[0]), "=r"(r[1]), "=r"(r[2]), "=r"(r[3]) : "r"(addr));
}
__device__ __forceinline__ void ldm_x4t(uint32_t r[4], uint32_t addr) {
    asm volatile("ldmatrix.sync.aligned.m8n8.x4.trans.shared.b16 {%0,%1,%2,%3}, [%4];"
                 : "=r"(r[0]), "=r"(r[1]), "=r"(r[2]), "=r"(r[3]) : "r"(addr));
}
__device__ __forceinline__ void mma_bf16(float c[4], const uint32_t a[4], const uint32_t b[2]) {
    asm volatile("mma.sync.aligned.m16n8k16.row.col.f32.bf16.bf16.f32 "
                 "{%0,%1,%2,%3}, {%4,%5,%6,%7}, {%8,%9}, {%0,%1,%2,%3};"
                 : "+f"(c[0]), "+f"(c[1]), "+f"(c[2]), "+f"(c[3])
                 : "r"(a[0]), "r"(a[1]), "r"(a[2]), "r"(a[3]), "r"(b[0]), "r"(b[1]));
}

// ---------------- split helpers ----------------
__device__ __forceinline__ void split1(float x, bf16& h, bf16& l) {
    h = __float2bfloat16(x);
    l = __float2bfloat16(x - __bfloat162float(h));
}

__global__ void split_kernel(const float* __restrict__ src,
                             bf16* __restrict__ hi, bf16* __restrict__ lo) {
    size_t i = ((size_t)blockIdx.x * blockDim.x + threadIdx.x) * 4;
    float4 v = *(const float4*)(src + i);
    bf16 h[4], l[4];
    split1(v.x, h[0], l[0]); split1(v.y, h[1], l[1]);
    split1(v.z, h[2], l[2]); split1(v.w, h[3], l[3]);
    *(uint2*)(hi + i) = *(uint2*)h;
    *(uint2*)(lo + i) = *(uint2*)l;
}

// extract q columns [0, DIM) of g_qkv, pre-scaled by QSCALE
__global__ void split_q_kernel() {
    size_t i = ((size_t)blockIdx.x * blockDim.x + threadIdx.x) * 4;  // over TOK*DIM
    size_t t = i / DIM, c = i % DIM;
    float4 v = *(const float4*)&g_qkv[t * QKVW + c];
    bf16 h[4], l[4];
    split1(v.x * QSCALE, h[0], l[0]); split1(v.y * QSCALE, h[1], l[1]);
    split1(v.z * QSCALE, h[2], l[2]); split1(v.w * QSCALE, h[3], l[3]);
    *(uint2*)(g_qh + i) = *(uint2*)h;
    *(uint2*)(g_ql + i) = *(uint2*)l;
}

// extract kv columns [DIM, QKVW) of g_qkv into compact hi/lo (TOK x DH)
__global__ void split_kv_kernel() {
    size_t i = ((size_t)blockIdx.x * blockDim.x + threadIdx.x) * 4;  // over TOK*DH
    size_t t = i / DH, c = i % DH;
    float4 v = *(const float4*)&g_qkv[t * QKVW + DIM + c];
    bf16 h[4], l[4];
    split1(v.x, h[0], l[0]); split1(v.y, h[1], l[1]);
    split1(v.z, h[2], l[2]); split1(v.w, h[3], l[3]);
    *(uint2*)(g_kvh + i) = *(uint2*)h;
    *(uint2*)(g_kvl + i) = *(uint2*)l;
}

// ---------------- reductions ----------------
__device__ __forceinline__ float blockReduceSum(float v) {
    __shared__ float sh[8];
    __syncthreads();
    #pragma unroll
    for (int o = 16; o > 0; o >>= 1) v += __shfl_xor_sync(0xffffffffu, v, o);
    int w = threadIdx.x >> 5, l = threadIdx.x & 31;
    if (l == 0) sh[w] = v;
    __syncthreads();
    if (w == 0) {
        v = (l < 8) ? sh[l] : 0.f;
        #pragma unroll
        for (int o = 4; o > 0; o >>= 1) v += __shfl_xor_sync(0xffffffffu, v, o);
        if (l == 0) sh[0] = v;
    }
    __syncthreads();
    return sh[0];
}
__device__ __forceinline__ float blockReduceMax(float v) {
    __shared__ float sh[8];
    __syncthreads();
    #pragma unroll
    for (int o = 16; o > 0; o >>= 1) v = fmaxf(v, __shfl_xor_sync(0xffffffffu, v, o));
    int w = threadIdx.x >> 5, l = threadIdx.x & 31;
    if (l == 0) sh[w] = v;
    __syncthreads();
    if (w == 0) {
        v = (l < 8) ? sh[l] : -INFINITY;
        #pragma unroll
        for (int o = 4; o > 0; o >>= 1) v = fmaxf(v, __shfl_xor_sync(0xffffffffu, v, o));
        if (l == 0) sh[0] = v;
    }
    __syncthreads();
    return sh[0];
}

// ---------------- 1. RMSNorm -> split bf16 hi/lo ----------------
__global__ void rmsnorm_kernel(const float* __restrict__ x, const float* __restrict__ g) {
    int row = blockIdx.x;
    const float* xr = x + (size_t)row * DIM;
    bf16* oh = g_xnh + (size_t)row * DIM;
    bf16* ol = g_xnl + (size_t)row * DIM;
    int t = threadIdx.x;
    float v[8];
    float ss = 0.f;
    #pragma unroll
    for (int i = 0; i < 8; i++) { v[i] = xr[t + i*256]; ss += v[i]*v[i]; }
    ss = blockReduceSum(ss);
    __shared__ float s_scale;
    if (t == 0) {
        float norm = sqrtf(ss * (1.0f / DIM));
        s_scale = 1.0f / fmaxf(norm, 1e-8f);
    }
    __syncthreads();
    float sc = s_scale;
    #pragma unroll
    for (int i = 0; i < 8; i++) {
        float o = v[i] * sc * g[t + i*256];
        bf16 h, l; split1(o, h, l);
        oh[t + i*256] = h; ol[t + i*256] = l;
    }
}

// ============ HMMA split-bf16 GEMM: C = Ah*Bh + Ah*Bl + Al*Bh (+D) ============
// A: MxK row-major bf16 hi/lo (lda). B: KxN row-major bf16 hi/lo (ldb).
// CTA tile 128x128, BK=32, 256 threads = 8 warps (4m x 2n), warp tile 32x64.
#define ASTRIDE 80      // bytes per A smem row (rows 128)
#define BSTRIDE 272     // bytes per B smem row (rows 32)
#define AH_OFF  0
#define AL_OFF  10240
#define BH_OFF  20480
#define BL_OFF  29184
#define STAGE   37888
#define GEMM_SMEM (2*STAGE)   // 75776 B

__device__ __forceinline__ void tc_body(
    const bf16* __restrict__ Ah, const bf16* __restrict__ Al,
    const bf16* __restrict__ Bh, const bf16* __restrict__ Bl,
    float* __restrict__ C, const float* __restrict__ Dadd,
    int K, int lda, int ldb, int ldc, int m0, int n0)
{
    extern __shared__ char smem[];
    uint32_t sb = smem_u32(smem);
    const int tid = threadIdx.x, wid = tid >> 5, lane = tid & 31;
    const int wm = wid >> 1, wn = wid & 1;

    float acc[2][8][4] = {};

    auto load_chunk = [&](int c, int buf) {
        uint32_t base = sb + buf * STAGE;
        int k0 = c * 32;
        #pragma unroll
        for (int i = 0; i < 2; i++) {
            int l = tid + i * 256;
            int row = l >> 2, kc = (l & 3) * 8;
            size_t go = (size_t)(m0 + row) * lda + k0 + kc;
            uint32_t so = (uint32_t)(row * ASTRIDE + kc * 2);
            cp16(base + AH_OFF + so, Ah + go);
            cp16(base + AL_OFF + so, Al + go);
        }
        #pragma unroll
        for (int i = 0; i < 2; i++) {
            int l = tid + i * 256;
            int kr = l >> 4, nc = (l & 15) * 8;
            size_t go = (size_t)(k0 + kr) * ldb + n0 + nc;
            uint32_t so = (uint32_t)(kr * BSTRIDE + nc * 2);
            cp16(base + BH_OFF + so, Bh + go);
            cp16(base + BL_OFF + so, Bl + go);
        }
        cp_commit();
    };

    const int NC = K >> 5;
    load_chunk(0, 0);
    cp_wait<0>(); __syncthreads();
    for (int c = 0; c < NC; c++) {
        int buf = c & 1;
        if (c + 1 < NC) load_chunk(c + 1, buf ^ 1);
        uint32_t base = sb + buf * STAGE;
        #pragma unroll
        for (int ks = 0; ks < 2; ks++) {
            uint32_t aH[2][4], aL[2][4], bH[8][2], bL[8][2];
            #pragma unroll
            for (int mt = 0; mt < 2; mt++) {
                int row = wm * 32 + mt * 16 + (lane & 15);
                int col = ks * 16 + (lane >> 4) * 8;
                uint32_t off = (uint32_t)(row * ASTRIDE + col * 2);
                ldm_x4(aH[mt], base + AH_OFF + off);
                ldm_x4(aL[mt], base + AL_OFF + off);
            }
            #pragma unroll
            for (int np = 0; np < 4; np++) {
                int kr = ks * 16 + (lane & 15);
                int nc = wn * 64 + np * 16 + (lane >> 4) * 8;
                uint32_t off = (uint32_t)(kr * BSTRIDE + nc * 2);
                uint32_t th[4], tl[4];
                ldm_x4t(th, base + BH_OFF + off);
                ldm_x4t(tl, base + BL_OFF + off);
                bH[np*2][0] = th[0]; bH[np*2][1] = th[1];
                bH[np*2+1][0] = th[2]; bH[np*2+1][1] = th[3];
                bL[np*2][0] = tl[0]; bL[np*2][1] = tl[1];
                bL[np*2+1][0] = tl[2]; bL[np*2+1][1] = tl[3];
            }
            #pragma unroll
            for (int mt = 0; mt < 2; mt++)
                #pragma unroll
                for (int nt = 0; nt < 8; nt++) {
                    mma_bf16(acc[mt][nt], aH[mt], bH[nt]);
                    mma_bf16(acc[mt][nt], aH[mt], bL[nt]);
                    mma_bf16(acc[mt][nt], aL[mt], bH[nt]);
                }
        }
        if (c + 1 < NC) { cp_wait<0>(); __syncthreads(); }
    }

    #pragma unroll
    for (int mt = 0; mt < 2; mt++) {
        int r0 = m0 + wm * 32 + mt * 16 + (lane >> 2);
        #pragma unroll
        for (int nt = 0; nt < 8; nt++) {
            int cc = n0 + wn * 64 + nt * 8 + (lane & 3) * 2;
            float2 v0 = make_float2(acc[mt][nt][0], acc[mt][nt][1]);
            float2 v1 = make_float2(acc[mt][nt][2], acc[mt][nt][3]);
            size_t o0 = (size_t)r0 * ldc + cc;
            size_t o1 = o0 + (size_t)8 * ldc;
            if (Dadd) {
                float2 d0 = *(const float2*)(Dadd + o0);
                float2 d1 = *(const float2*)(Dadd + o1);
                v0.x += d0.x; v0.y += d0.y; v1.x += d1.x; v1.y += d1.y;
            }
            *(float2*)(C + o0) = v0;
            *(float2*)(C + o1) = v1;
        }
    }
}

__global__ void __launch_bounds__(256, 1) tc_gemm(
    const bf16* __restrict__ Ah, const bf16* __restrict__ Al,
    const bf16* __restrict__ Bh, const bf16* __restrict__ Bl,
    float* __restrict__ C, const float* __restrict__ Dadd,
    int K, int lda, int ldb, int ldc)
{
    tc_body(Ah, Al, Bh, Bl, C, Dadd, K, lda, ldb, ldc, blockIdx.y * 128, blockIdx.x * 128);
}

// attn_v: ctx[b, rb*128.., h*DH..] = probs[z][rows, 0..(rb+1)*128) @ kv[b]
// Causal: K limited to (rb+1)*128 — softmax zero-pads probs to that boundary.
__global__ void __launch_bounds__(256, 1) attn_v_tc() {
    int z = blockIdx.z, b = z >> 4, h = z & 15;
    int rb = blockIdx.y;
    const bf16* Ah = g_ph + (size_t)z * NN * NN;
    const bf16* Al = g_pl + (size_t)z * NN * NN;
    const bf16* Bh = g_kvh + (size_t)b * NN * DH;
    const bf16* Bl = g_kvl + (size_t)b * NN * DH;
    float* C = g_ctx + (size_t)b * NN * DIM + h * DH;
    tc_body(Ah, Al, Bh, Bl, C, nullptr, (rb + 1) * 128, NN, DH, DIM, rb * 128, 0);
}

// ============ attn_sim HMMA (NT): sim = (q*QSCALE) @ kv^T + alibi ============
// Lower-triangle 128x128 tiles only. B (kv) is n-major: fragments via
// non-trans ldmatrix (flash-attn Q@K^T pattern). Softmax reads only j<=i, so
// no causal masking needed inside computed tiles; upper tiles never written.
#define SIM_STAGE (4*10240)
#define SIM_SMEM  (2*SIM_STAGE)   // 81920 B

__global__ void __launch_bounds__(256, 1) attn_sim_tc() {
    int z = blockIdx.z, b = z >> 4, h = z & 15;
    int it = blockIdx.y, jt = blockIdx.x;
    if (jt > it) return;
    extern __shared__ char smem[];
    uint32_t sb = smem_u32(smem);
    const int tid = threadIdx.x, wid = tid >> 5, lane = tid & 31;
    const int wm = wid >> 1, wn = wid & 1;
    const int m0 = it * 128, j0 = jt * 128;
    const bf16* Qh = g_qh + (size_t)b * NN * DIM + h * DH;
    const bf16* Ql = g_ql + (size_t)b * NN * DIM + h * DH;
    const bf16* Kh = g_kvh + (size_t)b * NN * DH;
    const bf16* Kl = g_kvl + (size_t)b * NN * DH;

    float acc[2][8][4] = {};

    auto load_chunk = [&](int c, int buf) {
        uint32_t base = sb + buf * SIM_STAGE;
        int k0 = c * 32;
        #pragma unroll
        for (int i = 0; i < 2; i++) {
            int l = tid + i * 256;
            int row = l >> 2, kc = (l & 3) * 8;
            uint32_t so = (uint32_t)(row * ASTRIDE + kc * 2);
            cp16(base + 0     + so, Qh + (size_t)(m0 + row) * DIM + k0 + kc);
            cp16(base + 10240 + so, Ql + (size_t)(m0 + row) * DIM + k0 + kc);
            cp16(base + 20480 + so, Kh + (size_t)(j0 + row) * DH + k0 + kc);
            cp16(base + 30720 + so, Kl + (size_t)(j0 + row) * DH + k0 + kc);
        }
        cp_commit();
    };

    load_chunk(0, 0);
    cp_wait<0>(); __syncthreads();
    for (int c = 0; c < 4; c++) {           // K = DH = 128, chunks of 32
        int buf = c & 1;
        if (c + 1 < 4) load_chunk(c + 1, buf ^ 1);
        uint32_t base = sb + buf * SIM_STAGE;
        #pragma unroll
        for (int ks = 0; ks < 2; ks++) {
            uint32_t aH[2][4], aL[2][4], bH[8][2], bL[8][2];
            int col = ks * 16 + (lane >> 4) * 8;
            #pragma unroll
            for (int mt = 0; mt < 2; mt++) {
                int row = wm * 32 + mt * 16 + (lane & 15);
                uint32_t off = (uint32_t)(row * ASTRIDE + col * 2);
                ldm_x4(aH[mt], base + 0     + off);
                ldm_x4(aL[mt], base + 10240 + off);
            }
            #pragma unroll
            for (int np = 0; np < 4; np++) {
                int row = wn * 64 + np * 16 + (lane & 15);
                uint32_t off = (uint32_t)(row * ASTRIDE + col * 2);
                uint32_t th[4], tl[4];
                ldm_x4(th, base + 20480 + off);
                ldm_x4(tl, base + 30720 + off);
                // non-trans on n-major rows: r0=(n0-7,k0-7) r1=(n8-15,k0-7)
                //                            r2=(n0-7,k8-15) r3=(n8-15,k8-15)
                bH[np*2][0]   = th[0]; bH[np*2][1]   = th[2];
                bH[np*2+1][0] = th[1]; bH[np*2+1][1] = th[3];
                bL[np*2][0]   = tl[0]; bL[np*2][1]   = tl[2];
                bL[np*2+1][0] = tl[1]; bL[np*2+1][1] = tl[3];
            }
            #pragma unroll
            for (int mt = 0; mt < 2; mt++)
                #pragma unroll
                for (int nt = 0; nt < 8; nt++) {
                    mma_bf16(acc[mt][nt], aH[mt], bH[nt]);
                    mma_bf16(acc[mt][nt], aH[mt], bL[nt]);
                    mma_bf16(acc[mt][nt], aL[mt], bH[nt]);
                }
        }
        if (c + 1 < 4) { cp_wait<0>(); __syncthreads(); }
    }

    float slope = exp2f(-0.5f * (float)(h + 1));
    float* S = g_sim + (size_t)z * NN * NN;
    #pragma unroll
    for (int mt = 0; mt < 2; mt++) {
        int i0 = m0 + wm * 32 + mt * 16 + (lane >> 2);
        #pragma unroll
        for (int nt = 0; nt < 8; nt++) {
            int j = j0 + wn * 64 + nt * 8 + (lane & 3) * 2;
            float2 v0, v1;
            v0.x = acc[mt][nt][0] - (float)(i0 - j) * slope;
            v0.y = acc[mt][nt][1] - (float)(i0 - j - 1) * slope;
            v1.x = acc[mt][nt][2] - (float)(i0 + 8 - j) * slope;
            v1.y = acc[mt][nt][3] - (float)(i0 + 8 - j - 1) * slope;
            *(float2*)&S[(size_t)i0 * NN + j] = v0;
            *(float2*)&S[(size_t)(i0 + 8) * NN + j] = v1;
        }
    }
}

// ---------------- 3. SwiGLU activation -> split bf16 hi/lo ----------------
__global__ void silu_split_kernel() {
    size_t i4 = ((size_t)blockIdx.x * blockDim.x + threadIdx.x) * 4;
    size_t r = i4 / FF, c = i4 % FF;
    const float4 val  = *(const float4*)&g_h[r * (2*(size_t)FF) + c];
    const float4 gate = *(const float4*)&g_h[r * (2*(size_t)FF) + FF + c];
    float o[4];
    o[0] = val.x * (gate.x / (1.f + expf(-gate.x)));
    o[1] = val.y * (gate.y / (1.f + expf(-gate.y)));
    o[2] = val.z * (gate.z / (1.f + expf(-gate.z)));
    o[3] = val.w * (gate.w / (1.f + expf(-gate.w)));
    bf16 h[4], l[4];
    #pragma unroll
    for (int i = 0; i < 4; i++) split1(o[i], h[i], l[i]);
    size_t off = r * (size_t)FF + c;
    *(uint2*)(g_ffah + off) = *(uint2*)h;
    *(uint2*)(g_ffal + off) = *(uint2*)l;
}

// ------- 7. causal-prefix softmax -> split bf16 probs, zero-padded to 128 ---
__global__ void softmax_kernel() {
    __shared__ float srow[NN];
    int row = blockIdx.x;                 // b*HEADS*NN + h*NN + i
    int i = row & (NN - 1);
    int L = i + 1;                        // causal prefix length
    int P = ((i >> 7) + 1) << 7;          // pad to 128 (attn_v K boundary)
    size_t rowoff = (size_t)row * NN;
    const float* sp = g_sim + rowoff;
    bf16* oh = g_ph + rowoff;
    bf16* ol = g_pl + rowoff;
    int t = threadIdx.x;

    float m = -INFINITY;
    for (int j = t; j < L; j += 256) { float v = sp[j]; srow[j] = v; m = fmaxf(m, v); }
    m = blockReduceMax(m);
    float s = 0.f;
    for (int j = t; j < L; j += 256) { float e = expf(srow[j] - m); srow[j] = e; s += e; }
    s = blockReduceSum(s);
    float inv = 1.f / s;
    for (int j = t; j < P; j += 256) {
        float pv = (j < L) ? srow[j] * inv : 0.f;
        bf16 h, l; split1(pv, h, l);
        oh[j] = h; ol[j] = l;
    }
}

// ---------------- launch ----------------
extern "C" void kernel_launch(void* const* d_in, const int* in_sizes, int n_in,
                              void* d_out, int out_size) {
    const float* x          = (const float*)d_in[0];
    const float* g          = (const float*)d_in[1];
    const float* w_qkv      = (const float*)d_in[2];
    const float* w_attn_out = (const float*)d_in[3];
    const float* w_ff1      = (const float*)d_in[4];
    const float* w_ff2      = (const float*)d_in[5];
    float* out = (float*)d_out;

    static bool attr_done = false;
    if (!attr_done) {
        cudaFuncSetAttribute(tc_gemm,     cudaFuncAttributeMaxDynamicSharedMemorySize, GEMM_SMEM);
        cudaFuncSetAttribute(attn_v_tc,   cudaFuncAttributeMaxDynamicSharedMemorySize, GEMM_SMEM);
        cudaFuncSetAttribute(attn_sim_tc, cudaFuncAttributeMaxDynamicSharedMemorySize, SIM_SMEM);
        attr_done = true;
    }

    float *hbuf, *ffout, *qkv, *ctx;
    bf16 *xnh, *xnl, *ffah, *ffal, *ctxh, *ctxl;
    bf16 *wff1h, *wff1l, *wff2h, *wff2l, *wqkvh, *wqkvl, *waoh, *waol;
    cudaGetSymbolAddress((void**)&hbuf,  g_h);
    cudaGetSymbolAddress((void**)&ffout, g_ffout);
    cudaGetSymbolAddress((void**)&qkv,   g_qkv);
    cudaGetSymbolAddress((void**)&ctx,   g_ctx);
    cudaGetSymbolAddress((void**)&xnh,   g_xnh);
    cudaGetSymbolAddress((void**)&xnl,   g_xnl);
    cudaGetSymbolAddress((void**)&ffah,  g_ffah);
    cudaGetSymbolAddress((void**)&ffal,  g_ffal);
    cudaGetSymbolAddress((void**)&ctxh,  g_ctxh);
    cudaGetSymbolAddress((void**)&ctxl,  g_ctxl);
    cudaGetSymbolAddress((void**)&wff1h, g_wff1h);
    cudaGetSymbolAddress((void**)&wff1l, g_wff1l);
    cudaGetSymbolAddress((void**)&wff2h, g_wff2h);
    cudaGetSymbolAddress((void**)&wff2l, g_wff2l);
    cudaGetSymbolAddress((void**)&wqkvh, g_wqkvh);
    cudaGetSymbolAddress((void**)&wqkvl, g_wqkvl);
    cudaGetSymbolAddress((void**)&waoh,  g_waoh);
    cudaGetSymbolAddress((void**)&waol,  g_waol);

    // weight splits (fp32 -> bf16 hi/lo)
    split_kernel<<<(size_t)DIM*2*FF/1024, 256>>>(w_ff1,      wff1h, wff1l);
    split_kernel<<<(size_t)FF*DIM/1024,   256>>>(w_ff2,      wff2h, wff2l);
    split_kernel<<<(size_t)DIM*QKVW/1024, 256>>>(w_qkv,      wqkvh, wqkvl);
    split_kernel<<<(size_t)DIM*DIM/1024,  256>>>(w_attn_out, waoh,  waol);

    // 1. xn = rmsnorm(x)*g  (split output)
    rmsnorm_kernel<<<TOK, 256>>>(x, g);
    // 2. h = xn @ w_ff1
    tc_gemm<<<dim3(2*FF/128, TOK/128), 256, GEMM_SMEM>>>(
        xnh, xnl, wff1h, wff1l, hbuf, nullptr, DIM, DIM, 2*FF, 2*FF);
    // 3. ffact = silu(gate)*val  (split output)
    silu_split_kernel<<<(size_t)TOK*FF/1024, 256>>>();
    // 4. ffout = ffact @ w_ff2
    tc_gemm<<<dim3(DIM/128, TOK/128), 256, GEMM_SMEM>>>(
        ffah, ffal, wff2h, wff2l, ffout, nullptr, FF, FF, DIM, DIM);
    // 5. qkv = xn @ w_qkv
    tc_gemm<<<dim3(QKVW/128, TOK/128), 256, GEMM_SMEM>>>(
        xnh, xnl, wqkvh, wqkvl, qkv, nullptr, DIM, DIM, QKVW, QKVW);
    // 5b. split q (pre-scaled) and kv
    split_q_kernel<<<(size_t)TOK*DIM/1024, 256>>>();
    split_kv_kernel<<<(size_t)TOK*DH/1024, 256>>>();
    // 6. sim lower-triangle tiles via HMMA (+alibi; causal handled downstream)
    attn_sim_tc<<<dim3(NN/128, NN/128, BB*HEADS), 256, SIM_SMEM>>>();
    // 7. causal softmax -> probs hi/lo, zero-padded to 128 boundary
    softmax_kernel<<<BB*HEADS*NN, 256>>>();
    // 8. ctx = probs @ kv (causal K limit per row-block)
    attn_v_tc<<<dim3(1, NN/128, BB*HEADS), 256, GEMM_SMEM>>>();
    // 9. split ctx, then out = ctx @ w_attn_out + ffout
    split_kernel<<<(size_t)TOK*DIM/1024, 256>>>(ctx, ctxh, ctxl);
    tc_gemm<<<dim3(DIM/128, TOK/128), 256, GEMM_SMEM>>>(
        ctxh, ctxl, waoh, waol, out, ffout, DIM, DIM, DIM, DIM);
}

// round 11
// speedup vs baseline: 2.6086x; 1.0020x over previous
#include <cuda_runtime.h>
#include <cuda_bf16.h>
#include <cstdint>
#include <math.h>

// ---------------- problem constants ----------------
#define BB      2
#define NN      2048
#define DIM     2048
#define HEADS   16
#define DH      128
#define TOK     (BB*NN)          // 4096
#define FF      8192             // FF_MULT*DIM
#define QKVW    (DIM+DH)         // 2176
#define QSCALE  0.08838834764831845f   // 128^-0.5

typedef __nv_bfloat16 bf16;

// ---------------- scratch (static device memory; no allocs) ----------------
__device__ bf16  g_xnh  [(size_t)TOK*DIM];
__device__ bf16  g_xnl  [(size_t)TOK*DIM];
__device__ float g_h    [(size_t)TOK*2*FF];
__device__ bf16  g_ffah [(size_t)TOK*FF];
__device__ bf16  g_ffal [(size_t)TOK*FF];
__device__ float g_ffout[(size_t)TOK*DIM];
__device__ float g_sim  [(size_t)BB*HEADS*NN*NN];
__device__ bf16  g_ph   [(size_t)BB*HEADS*NN*NN];   // softmax probs hi
__device__ bf16  g_pl   [(size_t)BB*HEADS*NN*NN];   // softmax probs lo
__device__ bf16  g_qh   [(size_t)TOK*DIM];          // q (pre-scaled) hi
__device__ bf16  g_ql   [(size_t)TOK*DIM];          // q lo
__device__ bf16  g_kvh  [(size_t)TOK*DH];
__device__ bf16  g_kvl  [(size_t)TOK*DH];
__device__ bf16  g_ctxh [(size_t)TOK*DIM];
__device__ bf16  g_ctxl [(size_t)TOK*DIM];
__device__ bf16  g_wff1h[(size_t)DIM*2*FF];
__device__ bf16  g_wff1l[(size_t)DIM*2*FF];
__device__ bf16  g_wff2h[(size_t)FF*DIM];
__device__ bf16  g_wff2l[(size_t)FF*DIM];
__device__ bf16  g_wqkvh[(size_t)DIM*QKVW];
__device__ bf16  g_wqkvl[(size_t)DIM*QKVW];
__device__ bf16  g_waoh [(size_t)DIM*DIM];
__device__ bf16  g_waol [(size_t)DIM*DIM];

// ---------------- PTX helpers ----------------
__device__ __forceinline__ uint32_t smem_u32(const void* p) {
    uint32_t a;
    asm("{ .reg .u64 t; cvta.to.shared.u64 t, %1; cvt.u32.u64 %0, t; }" : "=r"(a) : "l"(p));
    return a;
}
__device__ __forceinline__ void cp16(uint32_t dst, const void* src) {
    asm volatile("cp.async.cg.shared.global [%0], [%1], 16;" :: "r"(dst), "l"(src));
}
__device__ __forceinline__ void cp_commit() { asm volatile("cp.async.commit_group;"); }
template<int W> __device__ __forceinline__ void cp_wait() {
    asm volatile("cp.async.wait_group %0;" :: "n"(W));
}
__device__ __forceinline__ void ldm_x4(uint32_t r[4], uint32_t addr) {
    asm volatile("ldmatrix.sync.aligned.m8n8.x4.shared.b16 {%0,%1,%2,%3}, [%4];"
                 : "=r"(r[0]), "=r"(r[1]), "=r"(r[2]), "=r"(r[3]) : "r"(addr));
}
__device__ __forceinline__ void ldm_x4t(uint32_t r[4], uint32_t addr) {
    asm volatile("ldmatrix.sync.aligned.m8n8.x4.trans.shared.b16 {%0,%1,%2,%3}, [%4];"
                 : "=r"(r[0]), "=r"(r[1]), "=r"(r[2]), "=r"(r[3]) : "r"(addr));
}
__device__ __forceinline__ void mma_bf16(float c[4], const uint32_t a[4], const uint32_t b[2]) {
    asm volatile("mma.sync.aligned.m16n8k16.row.col.f32.bf16.bf16.f32 "
                 "{%0,%1,%2,%3}, {%4,%5,%6,%7}, {%8,%9}, {%0,%1,%2,%3};"
                 : "+f"(c[0]), "+f"(c[1]), "+f"(c[2]), "+f"(c[3])
                 : "r"(a[0]), "r"(a[1]), "r"(a[2]), "r"(a[3]), "r"(b[0]), "r"(b[1]));
}

// ---------------- split helpers ----------------
__device__ __forceinline__ void split1(float x, bf16& h, bf16& l) {
    h = __float2bfloat16(x);
    l = __float2bfloat16(x - __bfloat162float(h));
}
// split a float2 and store packed (2 bf16 per 4B store)
__device__ __forceinline__ void split2_store(float2 v, bf16* hp, bf16* lp) {
    bf16 h[2], l[2];
    split1(v.x, h[0], l[0]); split1(v.y, h[1], l[1]);
    *(uint32_t*)hp = *(uint32_t*)h;
    *(uint32_t*)lp = *(uint32_t*)l;
}

__global__ void split_kernel(const float* __restrict__ src,
                             bf16* __restrict__ hi, bf16* __restrict__ lo) {
    size_t i = ((size_t)blockIdx.x * blockDim.x + threadIdx.x) * 4;
    float4 v = *(const float4*)(src + i);
    bf16 h[4], l[4];
    split1(v.x, h[0], l[0]); split1(v.y, h[1], l[1]);
    split1(v.z, h[2], l[2]); split1(v.w, h[3], l[3]);
    *(uint2*)(hi + i) = *(uint2*)h;
    *(uint2*)(lo + i) = *(uint2*)l;
}

// ---------------- reductions ----------------
__device__ __forceinline__ float blockReduceSum(float v) {
    __shared__ float sh[8];
    __syncthreads();
    #pragma unroll
    for (int o = 16; o > 0; o >>= 1) v += __shfl_xor_sync(0xffffffffu, v, o);
    int w = threadIdx.x >> 5, l = threadIdx.x & 31;
    if (l == 0) sh[w] = v;
    __syncthreads();
    if (w == 0) {
        v = (l < 8) ? sh[l] : 0.f;
        #pragma unroll
        for (int o = 4; o > 0; o >>= 1) v += __shfl_xor_sync(0xffffffffu, v, o);
        if (l == 0) sh[0] = v;
    }
    __syncthreads();
    return sh[0];
}
__device__ __forceinline__ float blockReduceMax(float v) {
    __shared__ float sh[8];
    __syncthreads();
    #pragma unroll
    for (int o = 16; o > 0; o >>= 1) v = fmaxf(v, __shfl_xor_sync(0xffffffffu, v, o));
    int w = threadIdx.x >> 5, l = threadIdx.x & 31;
    if (l == 0) sh[w] = v;
    __syncthreads();
    if (w == 0) {
        v = (l < 8) ? sh[l] : -INFINITY;
        #pragma unroll
        for (int o = 4; o > 0; o >>= 1) v = fmaxf(v, __shfl_xor_sync(0xffffffffu, v, o));
        if (l == 0) sh[0] = v;
    }
    __syncthreads();
    return sh[0];
}

// ---------------- 1. RMSNorm -> split bf16 hi/lo ----------------
__global__ void rmsnorm_kernel(const float* __restrict__ x, const float* __restrict__ g) {
    int row = blockIdx.x;
    const float* xr = x + (size_t)row * DIM;
    bf16* oh = g_xnh + (size_t)row * DIM;
    bf16* ol = g_xnl + (size_t)row * DIM;
    int t = threadIdx.x;
    float v[8];
    float ss = 0.f;
    #pragma unroll
    for (int i = 0; i < 8; i++) { v[i] = xr[t + i*256]; ss += v[i]*v[i]; }
    ss = blockReduceSum(ss);
    __shared__ float s_scale;
    if (t == 0) {
        float norm = sqrtf(ss * (1.0f / DIM));
        s_scale = 1.0f / fmaxf(norm, 1e-8f);
    }
    __syncthreads();
    float sc = s_scale;
    #pragma unroll
    for (int i = 0; i < 8; i++) {
        float o = v[i] * sc * g[t + i*256];
        bf16 h, l; split1(o, h, l);
        oh[t + i*256] = h; ol[t + i*256] = l;
    }
}

// ============ HMMA split-bf16 GEMM: C = Ah*Bh + Ah*Bl + Al*Bh (+D) ============
// A: MxK row-major bf16 hi/lo (lda). B: KxN row-major bf16 hi/lo (ldb).
// CTA tile 128x128, BK=32, 256 threads = 8 warps (4m x 2n), warp tile 32x64.
// MODE 0: fp32 C (+optional D add).   MODE 1: qkv epilogue (q prescaled hi/lo,
// kv compact hi/lo).   MODE 2: bf16 hi/lo split C (ctx).
#define ASTRIDE 80      // bytes per A smem row (rows 128)
#define BSTRIDE 272     // bytes per B smem row (rows 32)
#define AH_OFF  0
#define AL_OFF  10240
#define BH_OFF  20480
#define BL_OFF  29184
#define STAGE   37888
#define GEMM_SMEM (2*STAGE)   // 75776 B

template<int MODE>
__device__ __forceinline__ void tc_body(
    const bf16* __restrict__ Ah, const bf16* __restrict__ Al,
    const bf16* __restrict__ Bh, const bf16* __restrict__ Bl,
    float* __restrict__ C, const float* __restrict__ Dadd,
    int K, int lda, int ldb, int ldc, int m0, int n0, size_t obase)
{
    extern __shared__ char smem[];
    uint32_t sb = smem_u32(smem);
    const int tid = threadIdx.x, wid = tid >> 5, lane = tid & 31;
    const int wm = wid >> 1, wn = wid & 1;

    float acc[2][8][4] = {};

    auto load_chunk = [&](int c, int buf) {
        uint32_t base = sb + buf * STAGE;
        int k0 = c * 32;
        #pragma unroll
        for (int i = 0; i < 2; i++) {
            int l = tid + i * 256;
            int row = l >> 2, kc = (l & 3) * 8;
            size_t go = (size_t)(m0 + row) * lda + k0 + kc;
            uint32_t so = (uint32_t)(row * ASTRIDE + kc * 2);
            cp16(base + AH_OFF + so, Ah + go);
            cp16(base + AL_OFF + so, Al + go);
        }
        #pragma unroll
        for (int i = 0; i < 2; i++) {
            int l = tid + i * 256;
            int kr = l >> 4, nc = (l & 15) * 8;
            size_t go = (size_t)(k0 + kr) * ldb + n0 + nc;
            uint32_t so = (uint32_t)(kr * BSTRIDE + nc * 2);
            cp16(base + BH_OFF + so, Bh + go);
            cp16(base + BL_OFF + so, Bl + go);
        }
        cp_commit();
    };

    const int NC = K >> 5;
    load_chunk(0, 0);
    cp_wait<0>(); __syncthreads();
    for (int c = 0; c < NC; c++) {
        int buf = c & 1;
        if (c + 1 < NC) load_chunk(c + 1, buf ^ 1);
        uint32_t base = sb + buf * STAGE;
        #pragma unroll
        for (int ks = 0; ks < 2; ks++) {
            uint32_t aH[2][4], aL[2][4], bH[8][2], bL[8][2];
            #pragma unroll
            for (int mt = 0; mt < 2; mt++) {
                int row = wm * 32 + mt * 16 + (lane & 15);
                int col = ks * 16 + (lane >> 4) * 8;
                uint32_t off = (uint32_t)(row * ASTRIDE + col * 2);
                ldm_x4(aH[mt], base + AH_OFF + off);
                ldm_x4(aL[mt], base + AL_OFF + off);
            }
            #pragma unroll
            for (int np = 0; np < 4; np++) {
                int kr = ks * 16 + (lane & 15);
                int nc = wn * 64 + np * 16 + (lane >> 4) * 8;
                uint32_t off = (uint32_t)(kr * BSTRIDE + nc * 2);
                uint32_t th[4], tl[4];
                ldm_x4t(th, base + BH_OFF + off);
                ldm_x4t(tl, base + BL_OFF + off);
                bH[np*2][0] = th[0]; bH[np*2][1] = th[1];
                bH[np*2+1][0] = th[2]; bH[np*2+1][1] = th[3];
                bL[np*2][0] = tl[0]; bL[np*2][1] = tl[1];
                bL[np*2+1][0] = tl[2]; bL[np*2+1][1] = tl[3];
            }
            #pragma unroll
            for (int mt = 0; mt < 2; mt++)
                #pragma unroll
                for (int nt = 0; nt < 8; nt++) {
                    mma_bf16(acc[mt][nt], aH[mt], bH[nt]);
                    mma_bf16(acc[mt][nt], aH[mt], bL[nt]);
                    mma_bf16(acc[mt][nt], aL[mt], bH[nt]);
                }
        }
        if (c + 1 < NC) { cp_wait<0>(); __syncthreads(); }
    }

    #pragma unroll
    for (int mt = 0; mt < 2; mt++) {
        int r0 = m0 + wm * 32 + mt * 16 + (lane >> 2);
        #pragma unroll
        for (int nt = 0; nt < 8; nt++) {
            int cc = n0 + wn * 64 + nt * 8 + (lane & 3) * 2;
            float2 v0 = make_float2(acc[mt][nt][0], acc[mt][nt][1]);
            float2 v1 = make_float2(acc[mt][nt][2], acc[mt][nt][3]);
            if (MODE == 0) {
                size_t o0 = (size_t)r0 * ldc + cc;
                size_t o1 = o0 + (size_t)8 * ldc;
                if (Dadd) {
                    float2 d0 = *(const float2*)(Dadd + o0);
                    float2 d1 = *(const float2*)(Dadd + o1);
                    v0.x += d0.x; v0.y += d0.y; v1.x += d1.x; v1.y += d1.y;
                }
                *(float2*)(C + o0) = v0;
                *(float2*)(C + o1) = v1;
            } else if (MODE == 1) {
                // qkv: cc<DIM -> q prescaled; cc>=DIM -> compact kv
                #pragma unroll
                for (int rr = 0; rr < 2; rr++) {
                    int r = r0 + rr * 8;
                    float2 v = rr ? v1 : v0;
                    if (cc < DIM) {
                        v.x *= QSCALE; v.y *= QSCALE;
                        size_t o = (size_t)r * DIM + cc;
                        split2_store(v, g_qh + o, g_ql + o);
                    } else {
                        size_t o = (size_t)r * DH + (cc - DIM);
                        split2_store(v, g_kvh + o, g_kvl + o);
                    }
                }
            } else {  // MODE 2: ctx bf16 split
                size_t o0 = obase + (size_t)r0 * ldc + cc;
                size_t o1 = o0 + (size_t)8 * ldc;
                split2_store(v0, g_ctxh + o0, g_ctxl + o0);
                split2_store(v1, g_ctxh + o1, g_ctxl + o1);
            }
        }
    }
}

// swap=0: n-tiles fastest (x=n).  swap=1: m-tiles fastest (x=m) — use when B
// is the large streamed operand (ff1) so a wave shares B panels via L2.
__global__ void __launch_bounds__(256, 1) tc_gemm(
    const bf16* __restrict__ Ah, const bf16* __restrict__ Al,
    const bf16* __restrict__ Bh, const bf16* __restrict__ Bl,
    float* __restrict__ C, const float* __restrict__ Dadd,
    int K, int lda, int ldb, int ldc, int swap)
{
    int m0 = (swap ? blockIdx.x : blockIdx.y) * 128;
    int n0 = (swap ? blockIdx.y : blockIdx.x) * 128;
    tc_body<0>(Ah, Al, Bh, Bl, C, Dadd, K, lda, ldb, ldc, m0, n0, 0);
}

// qkv = xn @ w_qkv with fused split epilogue (q prescaled, kv compact)
__global__ void __launch_bounds__(256, 1) tc_gemm_qkv() {
    tc_body<1>(g_xnh, g_xnl, g_wqkvh, g_wqkvl, nullptr, nullptr,
               DIM, DIM, QKVW, QKVW, blockIdx.y * 128, blockIdx.x * 128, 0);
}

// attn_v: ctx[b, rb*128.., h*DH..] = probs[z][rows, 0..(rb+1)*128) @ kv[b]
// Causal K limit; epilogue writes ctx hi/lo splits directly.
__global__ void __launch_bounds__(256, 1) attn_v_tc() {
    int z = blockIdx.z, b = z >> 4, h = z & 15;
    int rb = blockIdx.y;
    const bf16* Ah = g_ph + (size_t)z * NN * NN;
    const bf16* Al = g_pl + (size_t)z * NN * NN;
    const bf16* Bh = g_kvh + (size_t)b * NN * DH;
    const bf16* Bl = g_kvl + (size_t)b * NN * DH;
    size_t obase = (size_t)b * NN * DIM + h * DH;
    tc_body<2>(Ah, Al, Bh, Bl, nullptr, nullptr,
               (rb + 1) * 128, NN, DH, DIM, rb * 128, 0, obase);
}

// ============ attn_sim HMMA (NT): sim = (q*QSCALE) @ kv^T + alibi ============
// Lower-triangle 128x128 tiles only; softmax reads only j<=i.
#define SIM_STAGE (4*10240)
#define SIM_SMEM  (2*SIM_STAGE)   // 81920 B

__global__ void __launch_bounds__(256, 1) attn_sim_tc() {
    int z = blockIdx.z, b = z >> 4, h = z & 15;
    int it = blockIdx.y, jt = blockIdx.x;
    if (jt > it) return;
    extern __shared__ char smem[];
    uint32_t sb = smem_u32(smem);
    const int tid = threadIdx.x, wid = tid >> 5, lane = tid & 31;
    const int wm = wid >> 1, wn = wid & 1;
    const int m0 = it * 128, j0 = jt * 128;
    const bf16* Qh = g_qh + (size_t)b * NN * DIM + h * DH;
    const bf16* Ql = g_ql + (size_t)b * NN * DIM + h * DH;
    const bf16* Kh = g_kvh + (size_t)b * NN * DH;
    const bf16* Kl = g_kvl + (size_t)b * NN * DH;

    float acc[2][8][4] = {};

    auto load_chunk = [&](int c, int buf) {
        uint32_t base = sb + buf * SIM_STAGE;
        int k0 = c * 32;
        #pragma unroll
        for (int i = 0; i < 2; i++) {
            int l = tid + i * 256;
            int row = l >> 2, kc = (l & 3) * 8;
            uint32_t so = (uint32_t)(row * ASTRIDE + kc * 2);
            cp16(base + 0     + so, Qh + (size_t)(m0 + row) * DIM + k0 + kc);
            cp16(base + 10240 + so, Ql + (size_t)(m0 + row) * DIM + k0 + kc);
            cp16(base + 20480 + so, Kh + (size_t)(j0 + row) * DH + k0 + kc);
            cp16(base + 30720 + so, Kl + (size_t)(j0 + row) * DH + k0 + kc);
        }
        cp_commit();
    };

    load_chunk(0, 0);
    cp_wait<0>(); __syncthreads();
    for (int c = 0; c < 4; c++) {           // K = DH = 128, chunks of 32
        int buf = c & 1;
        if (c + 1 < 4) load_chunk(c + 1, buf ^ 1);
        uint32_t base = sb + buf * SIM_STAGE;
        #pragma unroll
        for (int ks = 0; ks < 2; ks++) {
            uint32_t aH[2][4], aL[2][4], bH[8][2], bL[8][2];
            int col = ks * 16 + (lane >> 4) * 8;
            #pragma unroll
            for (int mt = 0; mt < 2; mt++) {
                int row = wm * 32 + mt * 16 + (lane & 15);
                uint32_t off = (uint32_t)(row * ASTRIDE + col * 2);
                ldm_x4(aH[mt], base + 0     + off);
                ldm_x4(aL[mt], base + 10240 + off);
            }
            #pragma unroll
            for (int np = 0; np < 4; np++) {
                int row = wn * 64 + np * 16 + (lane & 15);
                uint32_t off = (uint32_t)(row * ASTRIDE + col * 2);
                uint32_t th[4], tl[4];
                ldm_x4(th, base + 20480 + off);
                ldm_x4(tl, base + 30720 + off);
                bH[np*2][0]   = th[0]; bH[np*2][1]   = th[2];
                bH[np*2+1][0] = th[1]; bH[np*2+1][1] = th[3];
                bL[np*2][0]   = tl[0]; bL[np*2][1]   = tl[2];
                bL[np*2+1][0] = tl[1]; bL[np*2+1][1] = tl[3];
            }
            #pragma unroll
            for (int mt = 0; mt < 2; mt++)
                #pragma unroll
                for (int nt = 0; nt < 8; nt++) {
                    mma_bf16(acc[mt][nt], aH[mt], bH[nt]);
                    mma_bf16(acc[mt][nt], aH[mt], bL[nt]);
                    mma_bf16(acc[mt][nt], aL[mt], bH[nt]);
                }
        }
        if (c + 1 < 4) { cp_wait<0>(); __syncthreads(); }
    }

    float slope = exp2f(-0.5f * (float)(h + 1));
    float* S = g_sim + (size_t)z * NN * NN;
    #pragma unroll
    for (int mt = 0; mt < 2; mt++) {
        int i0 = m0 + wm * 32 + mt * 16 + (lane >> 2);
        #pragma unroll
        for (int nt = 0; nt < 8; nt++) {
            int j = j0 + wn * 64 + nt * 8 + (lane & 3) * 2;
            float2 v0, v1;
            v0.x = acc[mt][nt][0] - (float)(i0 - j) * slope;
            v0.y = acc[mt][nt][1] - (float)(i0 - j - 1) * slope;
            v1.x = acc[mt][nt][2] - (float)(i0 + 8 - j) * slope;
            v1.y = acc[mt][nt][3] - (float)(i0 + 8 - j - 1) * slope;
            *(float2*)&S[(size_t)i0 * NN + j] = v0;
            *(float2*)&S[(size_t)(i0 + 8) * NN + j] = v1;
        }
    }
}

// ---------------- 3. SwiGLU activation -> split bf16 hi/lo ----------------
__global__ void silu_split_kernel() {
    size_t i4 = ((size_t)blockIdx.x * blockDim.x + threadIdx.x) * 4;
    size_t r = i4 / FF, c = i4 % FF;
    const float4 val  = *(const float4*)&g_h[r * (2*(size_t)FF) + c];
    const float4 gate = *(const float4*)&g_h[r * (2*(size_t)FF) + FF + c];
    float o[4];
    o[0] = val.x * (gate.x / (1.f + expf(-gate.x)));
    o[1] = val.y * (gate.y / (1.f + expf(-gate.y)));
    o[2] = val.z * (gate.z / (1.f + expf(-gate.z)));
    o[3] = val.w * (gate.w / (1.f + expf(-gate.w)));
    bf16 h[4], l[4];
    #pragma unroll
    for (int i = 0; i < 4; i++) split1(o[i], h[i], l[i]);
    size_t off = r * (size_t)FF + c;
    *(uint2*)(g_ffah + off) = *(uint2*)h;
    *(uint2*)(g_ffal + off) = *(uint2*)l;
}

// ------- 7. causal-prefix softmax -> split bf16 probs, zero-padded to 128 ---
__global__ void softmax_kernel() {
    __shared__ float srow[NN];
    int row = blockIdx.x;                 // b*HEADS*NN + h*NN + i
    int i = row & (NN - 1);
    int L = i + 1;                        // causal prefix length
    int P = ((i >> 7) + 1) << 7;          // pad to 128 (attn_v K boundary)
    size_t rowoff = (size_t)row * NN;
    const float* sp = g_sim + rowoff;
    bf16* oh = g_ph + rowoff;
    bf16* ol = g_pl + rowoff;
    int t = threadIdx.x;

    float m = -INFINITY;
    for (int j = t; j < L; j += 256) { float v = sp[j]; srow[j] = v; m = fmaxf(m, v); }
    m = blockReduceMax(m);
    float s = 0.f;
    for (int j = t; j < L; j += 256) { float e = expf(srow[j] - m); srow[j] = e; s += e; }
    s = blockReduceSum(s);
    float inv = 1.f / s;
    for (int j = t; j < P; j += 256) {
        float pv = (j < L) ? srow[j] * inv : 0.f;
        bf16 h, l; split1(pv, h, l);
        oh[j] = h; ol[j] = l;
    }
}

// ---------------- launch ----------------
extern "C" void kernel_launch(void* const* d_in, const int* in_sizes, int n_in,
                              void* d_out, int out_size) {
    const float* x          = (const float*)d_in[0];
    const float* g          = (const float*)d_in[1];
    const float* w_qkv      = (const float*)d_in[2];
    const float* w_attn_out = (const float*)d_in[3];
    const float* w_ff1      = (const float*)d_in[4];
    const float* w_ff2      = (const float*)d_in[5];
    float* out = (float*)d_out;

    static bool attr_done = false;
    if (!attr_done) {
        cudaFuncSetAttribute(tc_gemm,     cudaFuncAttributeMaxDynamicSharedMemorySize, GEMM_SMEM);
        cudaFuncSetAttribute(tc_gemm_qkv, cudaFuncAttributeMaxDynamicSharedMemorySize, GEMM_SMEM);
        cudaFuncSetAttribute(attn_v_tc,   cudaFuncAttributeMaxDynamicSharedMemorySize, GEMM_SMEM);
        cudaFuncSetAttribute(attn_sim_tc, cudaFuncAttributeMaxDynamicSharedMemorySize, SIM_SMEM);
        attr_done = true;
    }

    float *hbuf, *ffout;
    bf16 *xnh, *xnl, *ffah, *ffal, *ctxh, *ctxl;
    bf16 *wff1h, *wff1l, *wff2h, *wff2l, *wqkvh, *wqkvl, *waoh, *waol;
    cudaGetSymbolAddress((void**)&hbuf,  g_h);
    cudaGetSymbolAddress((void**)&ffout, g_ffout);
    cudaGetSymbolAddress((void**)&xnh,   g_xnh);
    cudaGetSymbolAddress((void**)&xnl,   g_xnl);
    cudaGetSymbolAddress((void**)&ffah,  g_ffah);
    cudaGetSymbolAddress((void**)&ffal,  g_ffal);
    cudaGetSymbolAddress((void**)&ctxh,  g_ctxh);
    cudaGetSymbolAddress((void**)&ctxl,  g_ctxl);
    cudaGetSymbolAddress((void**)&wff1h, g_wff1h);
    cudaGetSymbolAddress((void**)&wff1l, g_wff1l);
    cudaGetSymbolAddress((void**)&wff2h, g_wff2h);
    cudaGetSymbolAddress((void**)&wff2l, g_wff2l);
    cudaGetSymbolAddress((void**)&wqkvh, g_wqkvh);
    cudaGetSymbolAddress((void**)&wqkvl, g_wqkvl);
    cudaGetSymbolAddress((void**)&waoh,  g_waoh);
    cudaGetSymbolAddress((void**)&waol,  g_waol);

    // weight splits (fp32 -> bf16 hi/lo)
    split_kernel<<<(size_t)DIM*2*FF/1024, 256>>>(w_ff1,      wff1h, wff1l);
    split_kernel<<<(size_t)FF*DIM/1024,   256>>>(w_ff2,      wff2h, wff2l);
    split_kernel<<<(size_t)DIM*QKVW/1024, 256>>>(w_qkv,      wqkvh, wqkvl);
    split_kernel<<<(size_t)DIM*DIM/1024,  256>>>(w_attn_out, waoh,  waol);

    // 1. xn = rmsnorm(x)*g  (split output)
    rmsnorm_kernel<<<TOK, 256>>>(x, g);
    // 2. h = xn @ w_ff1   (m fastest: weight streams once, A stays in L2)
    tc_gemm<<<dim3(TOK/128, 2*FF/128), 256, GEMM_SMEM>>>(
        xnh, xnl, wff1h, wff1l, hbuf, nullptr, DIM, DIM, 2*FF, 2*FF, 1);
    // 3. ffact = silu(gate)*val  (split output)
    silu_split_kernel<<<(size_t)TOK*FF/1024, 256>>>();
    // 4. ffout = ffact @ w_ff2  (n fastest: A is the large streamed operand)
    tc_gemm<<<dim3(DIM/128, TOK/128), 256, GEMM_SMEM>>>(
        ffah, ffal, wff2h, wff2l, ffout, nullptr, FF, FF, DIM, DIM, 0);
    // 5. qkv = xn @ w_qkv, fused split epilogue (q prescaled, kv compact)
    tc_gemm_qkv<<<dim3(QKVW/128, TOK/128), 256, GEMM_SMEM>>>();
    // 6. sim lower-triangle tiles via HMMA (+alibi)
    attn_sim_tc<<<dim3(NN/128, NN/128, BB*HEADS), 256, SIM_SMEM>>>();
    // 7. causal softmax -> probs hi/lo, zero-padded to 128 boundary
    softmax_kernel<<<BB*HEADS*NN, 256>>>();
    // 8. ctx = probs @ kv (causal K limit), fused ctx split epilogue
    attn_v_tc<<<dim3(1, NN/128, BB*HEADS), 256, GEMM_SMEM>>>();
    // 9. out = ctx @ w_attn_out + ffout
    tc_gemm<<<dim3(DIM/128, TOK/128), 256, GEMM_SMEM>>>(
        ctxh, ctxl, waoh, waol, out, ffout, DIM, DIM, DIM, DIM, 0);
}